// round 10
// baseline (speedup 1.0000x reference)
#include <cuda_runtime.h>
#include <cuda_bf16.h>
#include <cstdint>
#include <cstddef>

// Problem constants
#define BB 4
#define CC 128
#define NN 4096      // H*W
#define CQ 16
#define TQ 128       // queries per CTA
#define TK 128       // keys per tile
#define NTILES (NN / TK)   // 32

// ---------------------------------------------------------------------------
// Device scratch (bf16 QKV staged between kernels)
// ---------------------------------------------------------------------------
__device__ __align__(16) __nv_bfloat16 g_qb[(size_t)BB * NN * CQ];  // [b][n][cq]
__device__ __align__(16) __nv_bfloat16 g_kb[(size_t)BB * NN * CQ];  // [b][n][cq]
__device__ __align__(16) __nv_bfloat16 g_vb[(size_t)BB * CC * NN];  // [b][c][n]

// ---------------------------------------------------------------------------
// Helpers
// ---------------------------------------------------------------------------
__device__ __forceinline__ uint32_t smem_u32(const void* p) {
    uint32_t a;
    asm("{ .reg .u64 t; cvta.to.shared.u64 t, %1; cvt.u32.u64 %0, t; }"
        : "=r"(a) : "l"(p));
    return a;
}
// pack two fp32 -> bf16x2 (lo in low half)
__device__ __forceinline__ uint32_t pack_bf2(float lo, float hi) {
    uint32_t r;
    asm("cvt.rn.satfinite.bf16x2.f32 %0, %1, %2;" : "=r"(r) : "f"(hi), "f"(lo));
    return r;
}
__device__ __forceinline__ void cp16(uint32_t dst, const void* src) {
    asm volatile("cp.async.cg.shared.global [%0], [%1], 16;"
                 :: "r"(dst), "l"(src));
}
#define CP_COMMIT() asm volatile("cp.async.commit_group;" ::: "memory")
#define CP_WAIT(n)  asm volatile("cp.async.wait_group %0;" :: "n"(n) : "memory")

// ---- packed f32x2 (Blackwell, PTX ISA 8.6, sm_100+) ----
__device__ __forceinline__ unsigned long long pk2(float lo, float hi) {
    unsigned long long r;
    asm("mov.b64 %0, {%1, %2};" : "=l"(r) : "f"(lo), "f"(hi));
    return r;
}
__device__ __forceinline__ unsigned long long fma2(
    unsigned long long a, unsigned long long b, unsigned long long c) {
    unsigned long long d;
    asm("fma.rn.f32x2 %0, %1, %2, %3;" : "=l"(d) : "l"(a), "l"(b), "l"(c));
    return d;
}
__device__ __forceinline__ void unpk2(float& lo, float& hi, unsigned long long v) {
    asm("mov.b64 {%0, %1}, %2;" : "=f"(lo), "=f"(hi) : "l"(v));
}

// mma.m16n8k16 bf16 -> fp32
__device__ __forceinline__ void mma16816(
    float* d,
    uint32_t a0, uint32_t a1, uint32_t a2, uint32_t a3,
    uint32_t b0, uint32_t b1,
    float c0, float c1, float c2, float c3)
{
    asm volatile(
        "mma.sync.aligned.m16n8k16.row.col.f32.bf16.bf16.f32 "
        "{%0,%1,%2,%3}, {%4,%5,%6,%7}, {%8,%9}, {%10,%11,%12,%13};"
        : "=f"(d[0]), "=f"(d[1]), "=f"(d[2]), "=f"(d[3])
        : "r"(a0), "r"(a1), "r"(a2), "r"(a3),
          "r"(b0), "r"(b1),
          "f"(c0), "f"(c1), "f"(c2), "f"(c3));
}

// ---------------------------------------------------------------------------
// Kernel 1: fused QKV 1x1 convs, f32x2-packed FMA inner loop.
// Out tile per CTA: 160 rows (16 q + 16 k + 128 v) x 128 n.
// Accumulators packed along the c-dim (pairs of output channels).
// grid (32, 4), block 256.
// ---------------------------------------------------------------------------
#define WPITCH 132
#define QKV_SMEM (128 * WPITCH * 4 + 128 * 32 * 4 + 2 * 16 * 128 * 4)

__global__ void __launch_bounds__(256, 1) qkv_kernel(
    const float* __restrict__ x,
    const float* __restrict__ wq, const float* __restrict__ bq,
    const float* __restrict__ wk, const float* __restrict__ bk,
    const float* __restrict__ wv, const float* __restrict__ bv)
{
    extern __shared__ float s[];
    float* w_st  = s;                       // [128 k][WPITCH]
    float* wqk   = s + 128 * WPITCH;        // [128 k][32]
    float* x_s   = wqk + 128 * 32;          // [2][16][128]
    const uint32_t xsb = smem_u32(x_s);

    const int tid = threadIdx.x;
    const int b   = blockIdx.y;
    const int n0  = blockIdx.x * 128;
    const int ti  = tid & 15;
    const int tj  = tid >> 4;
    const int c0  = tj * 8;
    const int nb  = ti * 8;
    const int r0  = tj * 2;

    for (int i = tid; i < CC * CC; i += 256) {
        const int c = i >> 7, k = i & 127;
        w_st[k * WPITCH + c] = wv[i];
    }
    for (int i = tid; i < CQ * CC; i += 256) {
        const int r = i >> 7, k = i & 127;
        wqk[k * 32 + r]      = wq[i];
        wqk[k * 32 + 16 + r] = wk[i];
    }

    const float* xb = x + (size_t)b * CC * NN + n0;

#pragma unroll
    for (int it = 0; it < 2; ++it) {
        const int i = tid + it * 256;
        const int r = i >> 5, cc = (i & 31) * 4;
        cp16(xsb + (uint32_t)(r * 128 + cc) * 4, xb + (size_t)r * NN + cc);
    }
    CP_COMMIT();

    // acc2[j2][k]: channel pair (c0+2j2, c0+2j2+1), n column k
    unsigned long long acc2[4][8];
    unsigned long long qk2[8];              // row pair (r0, r0+1)
#pragma unroll
    for (int k = 0; k < 8; ++k) {
        qk2[k] = 0ull;
#pragma unroll
        for (int j2 = 0; j2 < 4; ++j2) acc2[j2][k] = 0ull;
    }

    for (int t = 0; t < 8; ++t) {
        if (t + 1 < 8) {
            const uint32_t dst = xsb + (uint32_t)(((t + 1) & 1) * 2048) * 4;
#pragma unroll
            for (int it = 0; it < 2; ++it) {
                const int i = tid + it * 256;
                const int r = i >> 5, cc = (i & 31) * 4;
                cp16(dst + (uint32_t)(r * 128 + cc) * 4,
                     xb + (size_t)(16 * (t + 1) + r) * NN + cc);
            }
            CP_COMMIT();
            CP_WAIT(1);
        } else {
            CP_WAIT(0);
        }
        __syncthreads();

        const float* xs   = x_s + (t & 1) * 2048;
        const float* wkp  = w_st + 16 * t * WPITCH;
        const float* wqkp = wqk + 16 * t * 32;
#pragma unroll
        for (int kk = 0; kk < 16; ++kk) {
            const float4 w0 = *(const float4*)(wkp + kk * WPITCH + c0);
            const float4 w1 = *(const float4*)(wkp + kk * WPITCH + c0 + 4);
            const unsigned long long w2[4] = {
                pk2(w0.x, w0.y), pk2(w0.z, w0.w),
                pk2(w1.x, w1.y), pk2(w1.z, w1.w)};
            const unsigned long long uq2 =
                pk2(wqkp[kk * 32 + r0], wqkp[kk * 32 + r0 + 1]);
            const float4 x0 = *(const float4*)(xs + kk * 128 + nb);
            const float4 x1 = *(const float4*)(xs + kk * 128 + nb + 4);
            const float xr[8] = {x0.x, x0.y, x0.z, x0.w, x1.x, x1.y, x1.z, x1.w};
#pragma unroll
            for (int k = 0; k < 8; ++k) {
                const unsigned long long xb2 = pk2(xr[k], xr[k]);
                qk2[k] = fma2(uq2, xb2, qk2[k]);
#pragma unroll
                for (int j2 = 0; j2 < 4; ++j2)
                    acc2[j2][k] = fma2(w2[j2], xb2, acc2[j2][k]);
            }
        }
        __syncthreads();
    }

    // ---- V epilogue: unpack, bias, pack bf16, store [c][n] ----
#pragma unroll
    for (int j2 = 0; j2 < 4; ++j2) {
        float lo[8], hi[8];
#pragma unroll
        for (int k = 0; k < 8; ++k) unpk2(lo[k], hi[k], acc2[j2][k]);
        const float b0 = bv[c0 + 2 * j2];
        const float b1 = bv[c0 + 2 * j2 + 1];
        uint4 u0, u1;
        u0.x = pack_bf2(lo[0] + b0, lo[1] + b0);
        u0.y = pack_bf2(lo[2] + b0, lo[3] + b0);
        u0.z = pack_bf2(lo[4] + b0, lo[5] + b0);
        u0.w = pack_bf2(lo[6] + b0, lo[7] + b0);
        u1.x = pack_bf2(hi[0] + b1, hi[1] + b1);
        u1.y = pack_bf2(hi[2] + b1, hi[3] + b1);
        u1.z = pack_bf2(hi[4] + b1, hi[5] + b1);
        u1.w = pack_bf2(hi[6] + b1, hi[7] + b1);
        *(uint4*)((char*)g_vb + (((size_t)b * CC + c0 + 2 * j2)     * NN + n0 + nb) * 2) = u0;
        *(uint4*)((char*)g_vb + (((size_t)b * CC + c0 + 2 * j2 + 1) * NN + n0 + nb) * 2) = u1;
    }

    // ---- QK epilogue: transpose 32x128 through smem, pack [n][16] ----
    {
        const float bias0 = (r0 < 16) ? __ldg(bq + r0) : __ldg(bk + r0 - 16);
        const float bias1 = (r0 + 1 < 16) ? __ldg(bq + r0 + 1) : __ldg(bk + r0 - 15);
        float* qk_s = x_s;                  // [32 rows][128 n]
#pragma unroll
        for (int k = 0; k < 8; ++k) {
            float lo, hi;
            unpk2(lo, hi, qk2[k]);
            qk_s[r0 * 128 + nb + k]       = lo + bias0;
            qk_s[(r0 + 1) * 128 + nb + k] = hi + bias1;
        }
        __syncthreads();

        const int half = tid >> 7;          // 0: q, 1: k
        const int nl   = tid & 127;
        const int rb   = half * 16;
        uint32_t pk[8];
#pragma unroll
        for (int j = 0; j < 8; ++j)
            pk[j] = pack_bf2(qk_s[(rb + 2 * j) * 128 + nl],
                             qk_s[(rb + 2 * j + 1) * 128 + nl]);
        char* dst = (char*)(half ? g_kb : g_qb) + ((size_t)b * NN + n0 + nl) * 32;
        *(uint4*)(dst)      = make_uint4(pk[0], pk[1], pk[2], pk[3]);
        *(uint4*)(dst + 16) = make_uint4(pk[4], pk[5], pk[6], pk[7]);
    }
}

// ---------------------------------------------------------------------------
// Kernel 2: HMMA flash attention, 512 threads / 16 warps.
// Warps = 8 query-groups (16 q each) x 2 key-halves (64 keys/tile each).
// 4 warps per SMSP -> 2x the independent HMMA streams of R8/R9.
// smem: Q [128][48] 6144 | K0/K1 6144 | V0/V1 [128c][272] 34816 ea. 88064 B.
// Combine overlay: O_s [128][132] fp32 + l_s [128].
// ---------------------------------------------------------------------------
#define KPITCH 48
#define VPITCH 272
#define SM_Q   0
#define SM_K0  6144
#define SM_K1  12288
#define SM_V0  18432
#define SM_V1  (SM_V0 + 34816)
#define SM_TOTAL (SM_V1 + 34816)
#define OSPITCH 132
#define SM_LS   (128 * OSPITCH * 4)

__device__ __forceinline__ void issue_tile(
    uint32_t smb, const char* kg, const char* vg, int t, int buf, int tid)
{
    const uint32_t kdst = smb + (buf ? SM_K1 : SM_K0);
    const uint32_t vdst = smb + (buf ? SM_V1 : SM_V0);
    const int m0 = t * TK;
    if (tid < 256) {   // K tile: 256 x 16B chunks
        const int n = tid >> 1, h = tid & 1;
        cp16(kdst + n * KPITCH + h * 16, kg + (size_t)(m0 + n) * 32 + h * 16);
    }
#pragma unroll
    for (int it = 0; it < 4; ++it) {  // V: 2048 x 16B chunks
        const int i = tid + it * 512;
        const int c = i >> 4, h = i & 15;
        cp16(vdst + c * VPITCH + h * 16,
             vg + (size_t)c * (NN * 2) + (size_t)m0 * 2 + h * 16);
    }
}

__global__ void __launch_bounds__(512, 1) attn_kernel(
    const float* __restrict__ x,
    const float* __restrict__ gamma,
    float* __restrict__ out)
{
    extern __shared__ char sm[];
    const uint32_t smb = smem_u32(sm);
    const int tid  = threadIdx.x;
    const int w    = tid >> 5;
    const int lane = tid & 31;
    const int p    = lane >> 2;      // row group
    const int q    = lane & 3;       // col pair
    const int qg   = w & 7;          // query group (16 queries)
    const int kh   = w >> 3;         // key half (s-steps 4kh..4kh+3)

    const int b  = blockIdx.y;
    const int n0 = blockIdx.x * TQ;

    const char* qg_p = (const char*)g_qb + ((size_t)b * NN + n0) * 32;
    const char* kg_p = (const char*)g_kb + (size_t)b * NN * 32;
    const char* vg_p = (const char*)g_vb + (size_t)b * CC * NN * 2;

    // ---- load Q tile (plain), issue K/V tile 0 ----
    if (tid < 256) {
        const int r = tid >> 1, h = tid & 1;
        *(uint4*)(sm + SM_Q + r * KPITCH + h * 16) =
            *(const uint4*)(qg_p + r * 32 + h * 16);
    }
    issue_tile(smb, kg_p, vg_p, 0, 0, tid);
    CP_COMMIT();
    __syncthreads();

    // ---- Q A-fragments ----
    uint32_t qa0, qa1, qa2, qa3;
    {
        const int r = 16 * qg + p;
        qa0 = *(const uint32_t*)(sm + SM_Q + r       * KPITCH + 4 * q);
        qa1 = *(const uint32_t*)(sm + SM_Q + (r + 8) * KPITCH + 4 * q);
        qa2 = *(const uint32_t*)(sm + SM_Q + r       * KPITCH + 16 + 4 * q);
        qa3 = *(const uint32_t*)(sm + SM_Q + (r + 8) * KPITCH + 16 + 4 * q);
    }

    float o[16][4];
#pragma unroll
    for (int jc = 0; jc < 16; ++jc)
#pragma unroll
        for (int k = 0; k < 4; ++k) o[jc][k] = 0.f;
    float l0 = 0.f, l1 = 0.f;

    for (int t = 0; t < NTILES; ++t) {
        if (t + 1 < NTILES) {
            issue_tile(smb, kg_p, vg_p, t + 1, (t + 1) & 1, tid);
            CP_COMMIT();
            CP_WAIT(1);
        } else {
            CP_WAIT(0);
        }
        __syncthreads();

        const char* smK = sm + ((t & 1) ? SM_K1 : SM_K0);
        const char* smV = sm + ((t & 1) ? SM_V1 : SM_V0);

#pragma unroll
        for (int sl = 0; sl < 4; ++sl) {
            const int s = 4 * kh + sl;
            const char* kr0 = smK + (16 * s + p)     * KPITCH + 4 * q;
            const char* kr1 = smK + (16 * s + 8 + p) * KPITCH + 4 * q;
            const uint32_t bka0 = *(const uint32_t*)(kr0);
            const uint32_t bka1 = *(const uint32_t*)(kr0 + 16);
            const uint32_t bkb0 = *(const uint32_t*)(kr1);
            const uint32_t bkb1 = *(const uint32_t*)(kr1 + 16);

            float d[8];
            mma16816(d,     qa0, qa1, qa2, qa3, bka0, bka1, 0.f, 0.f, 0.f, 0.f);
            mma16816(d + 4, qa0, qa1, qa2, qa3, bkb0, bkb1, 0.f, 0.f, 0.f, 0.f);

            const float e0 = __expf(d[0]), e1 = __expf(d[1]);
            const float e2 = __expf(d[2]), e3 = __expf(d[3]);
            const float e4 = __expf(d[4]), e5 = __expf(d[5]);
            const float e6 = __expf(d[6]), e7 = __expf(d[7]);
            l0 += (e0 + e1) + (e4 + e5);
            l1 += (e2 + e3) + (e6 + e7);

            const uint32_t pa0 = pack_bf2(e0, e1);
            const uint32_t pa1 = pack_bf2(e2, e3);
            const uint32_t pa2 = pack_bf2(e4, e5);
            const uint32_t pa3 = pack_bf2(e6, e7);

#pragma unroll
            for (int jc = 0; jc < 16; ++jc) {
                const char* vr = smV + (8 * jc + p) * VPITCH + 32 * s + 4 * q;
                const uint32_t bv0 = *(const uint32_t*)(vr);
                const uint32_t bv1 = *(const uint32_t*)(vr + 16);
                mma16816(o[jc], pa0, pa1, pa2, pa3, bv0, bv1,
                         o[jc][0], o[jc][1], o[jc][2], o[jc][3]);
            }
        }
        __syncthreads();
    }

    // ---- quad-reduce partial l ----
    l0 += __shfl_xor_sync(0xffffffffu, l0, 1);
    l0 += __shfl_xor_sync(0xffffffffu, l0, 2);
    l1 += __shfl_xor_sync(0xffffffffu, l1, 1);
    l1 += __shfl_xor_sync(0xffffffffu, l1, 2);

    // ---- cross-key-half combine through smem ----
    float* O_s = (float*)sm;                 // [128 rows][OSPITCH]
    float* l_s = (float*)(sm + SM_LS);       // [128]
    const int rr = 16 * qg + p;

    if (kh == 1) {
#pragma unroll
        for (int jc = 0; jc < 16; ++jc) {
            const int c = 8 * jc + 2 * q;
            O_s[rr * OSPITCH + c]           = o[jc][0];
            O_s[rr * OSPITCH + c + 1]       = o[jc][1];
            O_s[(rr + 8) * OSPITCH + c]     = o[jc][2];
            O_s[(rr + 8) * OSPITCH + c + 1] = o[jc][3];
        }
        if (q == 0) {
            l_s[rr]     = l0;
            l_s[rr + 8] = l1;
        }
    }
    __syncthreads();

    if (kh == 0) {
        const float g = __ldg(gamma);
        const float inv0 = 1.f / (l0 + l_s[rr]);
        const float inv1 = 1.f / (l1 + l_s[rr + 8]);
        const int nrow = n0 + rr;
#pragma unroll
        for (int jc = 0; jc < 16; ++jc) {
            const int c = 8 * jc + 2 * q;
            const float v0 = (o[jc][0] + O_s[rr * OSPITCH + c])           * inv0;
            const float v1 = (o[jc][1] + O_s[rr * OSPITCH + c + 1])       * inv0;
            const float v2 = (o[jc][2] + O_s[(rr + 8) * OSPITCH + c])     * inv1;
            const float v3 = (o[jc][3] + O_s[(rr + 8) * OSPITCH + c + 1]) * inv1;
            const size_t i0 = ((size_t)b * CC + c) * NN + nrow;
            out[i0]          = g * v0 + x[i0];
            out[i0 + NN]     = g * v1 + x[i0 + NN];
            out[i0 + 8]      = g * v2 + x[i0 + 8];
            out[i0 + NN + 8] = g * v3 + x[i0 + NN + 8];
        }
    }
}

// ---------------------------------------------------------------------------
// Launch
// ---------------------------------------------------------------------------
extern "C" void kernel_launch(void* const* d_in, const int* in_sizes, int n_in,
                              void* d_out, int out_size)
{
    const float* x     = (const float*)d_in[0];
    const float* wq    = (const float*)d_in[1];
    const float* bq    = (const float*)d_in[2];
    const float* wk    = (const float*)d_in[3];
    const float* bk    = (const float*)d_in[4];
    const float* wv    = (const float*)d_in[5];
    const float* bv    = (const float*)d_in[6];
    const float* gamma = (const float*)d_in[7];
    float* out = (float*)d_out;
    (void)in_sizes; (void)n_in; (void)out_size;

    cudaFuncSetAttribute(qkv_kernel,
                         cudaFuncAttributeMaxDynamicSharedMemorySize, QKV_SMEM);
    qkv_kernel<<<dim3(NN / 128, BB), 256, QKV_SMEM>>>(x, wq, bq, wk, bk, wv, bv);

    cudaFuncSetAttribute(attn_kernel,
                         cudaFuncAttributeMaxDynamicSharedMemorySize, SM_TOTAL);
    attn_kernel<<<dim3(NN / TQ, BB), 512, SM_TOTAL>>>(x, gamma, out);
}